// round 11
// baseline (speedup 1.0000x reference)
#include <cuda_runtime.h>
#include <cuda_fp16.h>
#include <cstdint>

// ---------------- problem dims (fixed) ----------------
#define B_DIM   1024
#define IN_DIM  4096
#define OUT_DIM 4096
#define NB      1024          // IN_DIM / 4 quant blocks per row
#define NX_BLOCKS (B_DIM * NB)      // 1,048,576  (x quant blocks)

// ---------------- GEMM tiling ----------------
#define BM 128
#define BN 256
#define BK 64                  // fine chunk: 128 bytes per smem row
#define BIG 128                // coarse stage = 2 fine chunks
#define NITER (IN_DIM / BIG)   // 32
#define A_BYTES (BM * 128)                    // 16 KB per fine chunk
#define B_BYTES (BN * 128)                    // 32 KB per fine chunk
#define CHUNK_BYTES (A_BYTES + B_BYTES)       // 48 KB
#define STAGE_BYTES (2 * CHUNK_BYTES)         // 96 KB coarse stage
#define SMEM_TOTAL (2 * STAGE_BYTES)          // 192 KB, 2 coarse stages

// ---------------- fp16 x scratch (device global: allocation-free) ----------------
__device__ __half g_Xh[(size_t)B_DIM * IN_DIM];    // 8 MB

// ---------------- helpers ----------------
__device__ __forceinline__ uint32_t smem_u32(const void* p) {
    uint32_t a;
    asm("{ .reg .u64 t; cvta.to.shared.u64 t, %1; cvt.u32.u64 %0, t; }" : "=r"(a) : "l"(p));
    return a;
}

__device__ __forceinline__ void cp_async16(uint32_t dst, const void* src) {
    asm volatile("cp.async.cg.shared.global [%0], [%1], 16;" :: "r"(dst), "l"(src) : "memory");
}
#define CP_COMMIT() asm volatile("cp.async.commit_group;" ::: "memory")
#define CP_WAIT(n)  asm volatile("cp.async.wait_group %0;" :: "n"(n) : "memory")

__device__ __forceinline__ void ldmatrix_x4(uint32_t& r0, uint32_t& r1, uint32_t& r2, uint32_t& r3,
                                            uint32_t addr) {
    asm volatile("ldmatrix.sync.aligned.m8n8.x4.shared.b16 {%0,%1,%2,%3}, [%4];"
                 : "=r"(r0), "=r"(r1), "=r"(r2), "=r"(r3) : "r"(addr));
}

__device__ __forceinline__ void mma16816(float* d, const uint32_t* a, const uint32_t* b) {
    asm volatile(
        "mma.sync.aligned.m16n8k16.row.col.f32.f16.f16.f32 "
        "{%0,%1,%2,%3}, {%4,%5,%6,%7}, {%8,%9}, {%0,%1,%2,%3};"
        : "+f"(d[0]), "+f"(d[1]), "+f"(d[2]), "+f"(d[3])
        : "r"(a[0]), "r"(a[1]), "r"(a[2]), "r"(a[3]), "r"(b[0]), "r"(b[1]));
}

// swizzled smem byte offset for (row, 16B-chunk)
__device__ __forceinline__ uint32_t swz(int row, int ch) {
    return (uint32_t)(row * 128 + ((ch ^ (row & 7)) << 4));
}

// ---------------- dequant math ----------------
// exact path (x pre-pass): v/s division
__device__ __forceinline__ float fq(float v, float s, float z) {
    float q = rintf(v / s + z);
    q = fminf(fmaxf(q, 0.0f), 255.0f);
    return (q - z) * s;
}
// fast path (W producer): rcp.approx + 1 Newton step ~= correctly-rounded 1/s
__device__ __forceinline__ float fq_rs(float v, float s, float z, float rs) {
    float q = rintf(fmaf(v, rs, z));
    q = fminf(fmaxf(q, 0.0f), 255.0f);
    return (q - z) * s;
}

union HalfPack { __half2 h2[2]; uint2 u; };

// ---------------- x dequant pre-pass ----------------
#define DQ_THREADS 256
#define DQ_PER_THREAD 8
#define DQ_PER_CTA (DQ_THREADS * DQ_PER_THREAD)   // 2048

__global__ void __launch_bounds__(DQ_THREADS, 4)
dequant_x_kernel(const float* __restrict__ x,  const float* __restrict__ xs,
                 const float* __restrict__ xz) {
    int j0 = blockIdx.x * DQ_PER_CTA + threadIdx.x;
    float4 v[DQ_PER_THREAD];
    float  s[DQ_PER_THREAD], z[DQ_PER_THREAD];
#pragma unroll
    for (int u = 0; u < DQ_PER_THREAD; u++) {
        int j = j0 + u * DQ_THREADS;
        v[u] = reinterpret_cast<const float4*>(x)[j];
        int blk = j & (NB - 1);
        s[u] = __ldg(xs + blk);
        z[u] = __ldg(xz + blk);
    }
#pragma unroll
    for (int u = 0; u < DQ_PER_THREAD; u++) {
        HalfPack p;
        p.h2[0] = __floats2half2_rn(fq(v[u].x, s[u], z[u]), fq(v[u].y, s[u], z[u]));
        p.h2[1] = __floats2half2_rn(fq(v[u].z, s[u], z[u]), fq(v[u].w, s[u], z[u]));
        reinterpret_cast<uint2*>(g_Xh)[j0 + u * DQ_THREADS] = p.u;
    }
}

// ---------------- A loader: g_Xh fp16 -> smem (coarse stage = 2 fine chunks) ----------------
__device__ __forceinline__ void load_A(uint32_t sbase, uint32_t slotOff, int m0, int kc) {
    int t = threadIdx.x;
#pragma unroll
    for (int i = 0; i < 8; i++) {                  // 2 x (128 rows x 8 chunks) = 2048
        int idx = t + i * 256;
        int sub = idx >> 10;
        int within = idx & 1023;
        int row = within >> 3, ch = within & 7;
        const __half* src = g_Xh + (size_t)(m0 + row) * IN_DIM + kc + sub * BK + ch * 8;
        cp_async16(sbase + slotOff + sub * CHUNK_BYTES + swz(row, ch), src);
    }
}

// ---------------- W producer: fp32 gmem -> fq -> fp16 smem (B region of a stage) ----------------
// One pass: warp covers one row's 128 K (32 float4, lane = float4 idx). Batch = 4 passes.
// issue: LDG only (registers); consume: fq + STS.
struct WBatch { float4 v[4]; float s[4], z[4]; };

__device__ __forceinline__ void w_issue(WBatch& B, const float* __restrict__ w,
                                        const float* __restrict__ ws, const float* __restrict__ wz,
                                        int n0, int kc, int wid, int lane, int b) {
#pragma unroll
    for (int k = 0; k < 4; k++) {
        int r = wid * 32 + b * 4 + k;
        int grow = n0 + r;
        B.v[k] = __ldg(reinterpret_cast<const float4*>(w + (size_t)grow * IN_DIM + kc) + lane);
        int sidx = grow * NB + (kc >> 2) + lane;
        B.s[k] = __ldg(ws + sidx);
        B.z[k] = __ldg(wz + sidx);
    }
}

__device__ __forceinline__ void w_consume(const WBatch& B, char* smem, uint32_t slotOff,
                                          int wid, int lane, int b) {
    int sub  = lane >> 4;          // fine chunk 0/1
    int l2   = lane & 15;
    int ch   = l2 >> 1;
    int off8 = (lane & 1) * 8;
#pragma unroll
    for (int k = 0; k < 4; k++) {
        int r = wid * 32 + b * 4 + k;
        float s = B.s[k], z = B.z[k];
        float rs;
        asm("rcp.approx.f32 %0, %1;" : "=f"(rs) : "f"(s));
        rs = rs * (2.0f - s * rs);                 // Newton: ~exact 1/s
        HalfPack p;
        p.h2[0] = __floats2half2_rn(fq_rs(B.v[k].x, s, z, rs), fq_rs(B.v[k].y, s, z, rs));
        p.h2[1] = __floats2half2_rn(fq_rs(B.v[k].z, s, z, rs), fq_rs(B.v[k].w, s, z, rs));
        uint32_t off = slotOff + sub * CHUNK_BYTES + A_BYTES + swz(r, ch) + off8;
        *reinterpret_cast<uint2*>(smem + off) = p.u;
    }
}

// ---------------- GEMM: 128x256 tile/CTA, warp 64x64, W dequant fused in-CTA ----------------
__global__ void __launch_bounds__(256, 1)
gemm_f16_kernel(const float* __restrict__ w,   const float* __restrict__ ws,
                const float* __restrict__ wz,
                const float* __restrict__ bias, float* __restrict__ out) {
    extern __shared__ char smem[];
    uint32_t sbase = smem_u32(smem);
    int tid = threadIdx.x;
    int wid = tid >> 5, lane = tid & 31;
    int m0 = blockIdx.y * BM;
    int n0 = blockIdx.x * BN;
    int wm = (wid & 1) * 64;      // 2 (m) x 4 (n) warps, warp tile 64 x 64
    int wn = (wid >> 1) * 64;

    int lrow = lane & 15;         // ldmatrix x4: lanes 0-15 rows, 16-31 chunk+1
    int lch  = lane >> 4;

    // ---- prologue: produce W stage 0 (2-deep batch pipeline), load A stage 0 ----
    {
        WBatch b0, b1;
        w_issue(b0, w, ws, wz, n0, 0, wid, lane, 0);
#pragma unroll 1
        for (int b = 0; b < 8; b++) {
            if (b & 1) {
                if (b < 7) w_issue(b0, w, ws, wz, n0, 0, wid, lane, b + 1);
                w_consume(b1, smem, 0, wid, lane, b);
            } else {
                if (b < 7) w_issue(b1, w, ws, wz, n0, 0, wid, lane, b + 1);
                w_consume(b0, smem, 0, wid, lane, b);
            }
        }
    }
    load_A(sbase, 0, m0, 0);
    CP_COMMIT();

    float acc[4][8][4];
#pragma unroll
    for (int i = 0; i < 4; i++)
#pragma unroll
        for (int j = 0; j < 8; j++)
#pragma unroll
            for (int k = 0; k < 4; k++) acc[i][j][k] = 0.0f;

#pragma unroll 1
    for (int c = 0; c < NITER; ++c) {
        CP_WAIT(0);               // A copies for stage c retired
        __syncthreads();          // A + producer-STS of stage c visible; stage c-1 consumed

        uint32_t slotOff  = (uint32_t)(c & 1) * STAGE_BYTES;
        uint32_t nslotOff = slotOff ^ STAGE_BYTES;
        int nkc = (c + 1) * BIG;
        bool has_next = (c + 1) < NITER;

        if (has_next) {           // prefetch A of next stage into the freed slot
            load_A(sbase, nslotOff, m0, nkc);
            CP_COMMIT();
        }

        WBatch wb;
        if (has_next) w_issue(wb, w, ws, wz, n0, nkc, wid, lane, 0);

        // 8 MMA groups (sub x ks); weave one W batch per group
#pragma unroll
        for (int g = 0; g < 8; g++) {
            int sub = g >> 2, ks = g & 3;
            uint32_t sA = sbase + slotOff + sub * CHUNK_BYTES;
            uint32_t sB = sA + A_BYTES;

            uint32_t a[4][4];
#pragma unroll
            for (int i = 0; i < 4; i++) {
                int row = wm + i * 16 + lrow;
                ldmatrix_x4(a[i][0], a[i][1], a[i][2], a[i][3],
                            sA + swz(row, ks * 2 + lch));
            }
            uint32_t b[8][2];
#pragma unroll
            for (int j = 0; j < 4; j++) {
                int row = wn + j * 16 + lrow;
                uint32_t r0, r1, r2, r3;
                ldmatrix_x4(r0, r1, r2, r3, sB + swz(row, ks * 2 + lch));
                b[2 * j][0] = r0;     b[2 * j][1] = r2;      // n-tile rows +0..7
                b[2 * j + 1][0] = r1; b[2 * j + 1][1] = r3;  // n-tile rows +8..15
            }
#pragma unroll
            for (int i = 0; i < 4; i++)
#pragma unroll
                for (int j = 0; j < 8; j++)
                    mma16816(acc[i][j], a[i], b[j]);

            // consume W batch g (loads have had a full MMA group to land), issue g+1
            if (has_next) {
                w_consume(wb, smem, nslotOff, wid, lane, g);
                if (g < 7) w_issue(wb, w, ws, wz, n0, nkc, wid, lane, g + 1);
            }
        }
    }

    // epilogue: C frag -> gmem with bias. lane: g = lane/4 (row), c2 = (lane%4)*2 (col)
    int g = lane >> 2, c2 = (lane & 3) * 2;
#pragma unroll
    for (int i = 0; i < 4; i++) {
        int row = m0 + wm + i * 16 + g;
        float* r0p = out + (size_t)row * OUT_DIM;
        float* r1p = out + (size_t)(row + 8) * OUT_DIM;
#pragma unroll
        for (int j = 0; j < 8; j++) {
            int col = n0 + wn + j * 8 + c2;
            float b0 = __ldg(&bias[col]), b1 = __ldg(&bias[col + 1]);
            float2 v0 = make_float2(acc[i][j][0] + b0, acc[i][j][1] + b1);
            float2 v1 = make_float2(acc[i][j][2] + b0, acc[i][j][3] + b1);
            *reinterpret_cast<float2*>(r0p + col) = v0;
            *reinterpret_cast<float2*>(r1p + col) = v1;
        }
    }
}

// ---------------- launch ----------------
extern "C" void kernel_launch(void* const* d_in, const int* in_sizes, int n_in,
                              void* d_out, int out_size) {
    const float* x    = (const float*)d_in[0];
    const float* w    = (const float*)d_in[1];
    const float* bias = (const float*)d_in[2];
    const float* ws   = (const float*)d_in[3];
    const float* wz   = (const float*)d_in[4];
    const float* as_  = (const float*)d_in[5];
    const float* az   = (const float*)d_in[6];
    float* out = (float*)d_out;

    dequant_x_kernel<<<NX_BLOCKS / DQ_PER_CTA, DQ_THREADS>>>(x, as_, az);

    cudaFuncSetAttribute(gemm_f16_kernel, cudaFuncAttributeMaxDynamicSharedMemorySize, SMEM_TOTAL);
    dim3 grid(OUT_DIM / BN, B_DIM / BM);   // 16 x 8 = 128 CTAs, one wave
    gemm_f16_kernel<<<grid, 256, SMEM_TOTAL>>>(w, ws, wz, bias, out);
}